// round 1
// baseline (speedup 1.0000x reference)
#include <cuda_runtime.h>
#include <cstdint>
#include <cstddef>

#define TDIM 4096
#define HDIM 2048
#define FDIM 7168

#define BM 128
#define BN 128
#define BK 32
#define STAGES 4
#define LDSA 36                      // 32 + 4 pad, conflict-free frag loads
#define STAGE_ELEMS (BM * LDSA)      // 4608 floats per tile per stage
#define SMEM_BYTES (STAGES * STAGE_ELEMS * 4 * 2)  // 147456

// ---------------- scratch (no allocations allowed) ----------------
__device__ float d_xr[(size_t)TDIM * HDIM];   // tf32-rounded x
__device__ float d_g[(size_t)TDIM * FDIM];    // x @ w1^T
__device__ float d_u[(size_t)TDIM * FDIM];    // x @ w3^T
__device__ float d_act[(size_t)TDIM * FDIM];  // silu(g)*u, tf32-rounded

// ---------------- helpers ----------------
__device__ __forceinline__ float tf32r(float f) {
    uint32_t u;
    asm("cvt.rna.tf32.f32 %0, %1;" : "=r"(u) : "f"(f));
    return __uint_as_float(u);
}

__device__ __forceinline__ void mma_tf32(float* d, const uint32_t* a, const uint32_t* b) {
    asm volatile(
        "mma.sync.aligned.m16n8k8.row.col.f32.tf32.tf32.f32 "
        "{%0,%1,%2,%3}, {%4,%5,%6,%7}, {%8,%9}, {%0,%1,%2,%3};\n"
        : "+f"(d[0]), "+f"(d[1]), "+f"(d[2]), "+f"(d[3])
        : "r"(a[0]), "r"(a[1]), "r"(a[2]), "r"(a[3]), "r"(b[0]), "r"(b[1]));
}

__device__ __forceinline__ void cp_async16(uint32_t smem_addr, const void* gptr) {
    asm volatile("cp.async.cg.shared.global [%0], [%1], 16;\n" :: "r"(smem_addr), "l"(gptr));
}
__device__ __forceinline__ void cp_commit() { asm volatile("cp.async.commit_group;\n"); }
template <int N>
__device__ __forceinline__ void cp_wait() { asm volatile("cp.async.wait_group %0;\n" :: "n"(N)); }

// ---------------- elementwise kernels ----------------
__global__ void cvt_tf32_kernel(const float4* __restrict__ in, float4* __restrict__ out, int n4) {
    int i = blockIdx.x * blockDim.x + threadIdx.x;
    if (i < n4) {
        float4 v = in[i];
        v.x = tf32r(v.x); v.y = tf32r(v.y); v.z = tf32r(v.z); v.w = tf32r(v.w);
        out[i] = v;
    }
}

__global__ void silu_mul_kernel(const float4* __restrict__ g, const float4* __restrict__ u,
                                float4* __restrict__ out, int n4) {
    int i = blockIdx.x * blockDim.x + threadIdx.x;
    if (i < n4) {
        float4 gv = g[i], uv = u[i], r;
        r.x = tf32r(gv.x / (1.0f + __expf(-gv.x)) * uv.x);
        r.y = tf32r(gv.y / (1.0f + __expf(-gv.y)) * uv.y);
        r.z = tf32r(gv.z / (1.0f + __expf(-gv.z)) * uv.z);
        r.w = tf32r(gv.w / (1.0f + __expf(-gv.w)) * uv.w);
        out[i] = r;
    }
}

// ---------------- block-scaled tf32 GEMM ----------------
// C[m,n] = sum_kb  S[n/128, kb] * sum_{k in kb} A[m,k]*B[n,k]
// A: [M,K] row-major (tf32-rounded fp32), B: [N,K] row-major (fp8-valued fp32, tf32-exact)
// grid = (M/128, N/128): bm fast so A tiles stay hot in L2, B streams once.
__global__ __launch_bounds__(256, 1)
void gemm_tf32_scaled(const float* __restrict__ A, const float* __restrict__ B,
                      const float* __restrict__ S, float* __restrict__ C,
                      int M, int N, int K)
{
    extern __shared__ float smem[];
    float* As = smem;                               // STAGES * 128 * 36
    float* Bs = smem + STAGES * STAGE_ELEMS;

    const int tid  = threadIdx.x;
    const int bm   = blockIdx.x;
    const int bn   = blockIdx.y;
    const int warp = tid >> 5, lane = tid & 31;
    const int wm = warp & 1;         // 2 warps over M (64 rows each)
    const int wn = warp >> 1;        // 4 warps over N (32 cols each)
    const int g  = lane >> 2, t4 = lane & 3;

    const float* Ablk = A + (size_t)bm * BM * K;
    const float* Bblk = B + (size_t)bn * BN * K;
    const int KB = K >> 7;           // number of 128-wide scale blocks
    const float* Srow = S + (size_t)bn * KB;
    const int KITERS = K / BK;

    auto issue_copy = [&](int stage, int kiter) {
        const int k0 = kiter * BK;
        float* as = As + stage * STAGE_ELEMS;
        float* bs = Bs + stage * STAGE_ELEMS;
        #pragma unroll
        for (int t = 0; t < 4; t++) {
            int idx = tid + t * 256;            // 0..1023
            int row = idx >> 3, c4 = (idx & 7) * 4;
            cp_async16((uint32_t)__cvta_generic_to_shared(as + row * LDSA + c4),
                       Ablk + (size_t)row * K + k0 + c4);
        }
        #pragma unroll
        for (int t = 0; t < 4; t++) {
            int idx = tid + t * 256;
            int row = idx >> 3, c4 = (idx & 7) * 4;
            cp_async16((uint32_t)__cvta_generic_to_shared(bs + row * LDSA + c4),
                       Bblk + (size_t)row * K + k0 + c4);
        }
    };

    float acc[4][4][4];
    #pragma unroll
    for (int mt = 0; mt < 4; mt++)
        #pragma unroll
        for (int nt = 0; nt < 4; nt++)
            #pragma unroll
            for (int i = 0; i < 4; i++) acc[mt][nt][i] = 0.0f;

    // prologue: stages 0..2  (stage index == kiter & 3)
    #pragma unroll
    for (int s = 0; s < STAGES - 1; s++) { issue_copy(s, s); cp_commit(); }

    float s_cur = __ldg(Srow);

    for (int kb = 0; kb < KB; kb++) {
        if (kb) {
            float sn = __ldg(Srow + kb);
            float r = s_cur / sn;
            s_cur = sn;
            #pragma unroll
            for (int mt = 0; mt < 4; mt++)
                #pragma unroll
                for (int nt = 0; nt < 4; nt++)
                    #pragma unroll
                    for (int i = 0; i < 4; i++) acc[mt][nt][i] *= r;
        }
        #pragma unroll
        for (int kk = 0; kk < 4; kk++) {
            const int kiter = kb * 4 + kk;      // stage = kiter & 3 = kk (KITERS mult of 4)
            cp_wait<STAGES - 2>();
            __syncthreads();

            const int nxt = kiter + (STAGES - 1);
            if (nxt < KITERS) issue_copy((kk + STAGES - 1) & 3, nxt);
            cp_commit();

            const float* as = As + kk * STAGE_ELEMS;
            const float* bs = Bs + kk * STAGE_ELEMS;
            #pragma unroll
            for (int ks = 0; ks < 4; ks++) {
                const int kc = ks * 8 + t4;
                uint32_t af[4][4], bf[4][2];
                #pragma unroll
                for (int mt = 0; mt < 4; mt++) {
                    int r0 = wm * 64 + mt * 16 + g;
                    af[mt][0] = __float_as_uint(as[r0 * LDSA + kc]);
                    af[mt][1] = __float_as_uint(as[(r0 + 8) * LDSA + kc]);
                    af[mt][2] = __float_as_uint(as[r0 * LDSA + kc + 4]);
                    af[mt][3] = __float_as_uint(as[(r0 + 8) * LDSA + kc + 4]);
                }
                #pragma unroll
                for (int nt = 0; nt < 4; nt++) {
                    int c0 = wn * 32 + nt * 8 + g;
                    bf[nt][0] = __float_as_uint(bs[c0 * LDSA + kc]);
                    bf[nt][1] = __float_as_uint(bs[c0 * LDSA + kc + 4]);
                }
                #pragma unroll
                for (int mt = 0; mt < 4; mt++)
                    #pragma unroll
                    for (int nt = 0; nt < 4; nt++)
                        mma_tf32(acc[mt][nt], af[mt], bf[nt]);
            }
        }
    }

    // epilogue: apply last scale, write fp32
    #pragma unroll
    for (int mt = 0; mt < 4; mt++) {
        int r0 = bm * BM + wm * 64 + mt * 16 + g;
        #pragma unroll
        for (int nt = 0; nt < 4; nt++) {
            int c0 = bn * BN + wn * 32 + nt * 8 + t4 * 2;
            float2 v0 = make_float2(acc[mt][nt][0] * s_cur, acc[mt][nt][1] * s_cur);
            float2 v1 = make_float2(acc[mt][nt][2] * s_cur, acc[mt][nt][3] * s_cur);
            *reinterpret_cast<float2*>(&C[(size_t)r0 * N + c0]) = v0;
            *reinterpret_cast<float2*>(&C[(size_t)(r0 + 8) * N + c0]) = v1;
        }
    }
}

// ---------------- launch ----------------
extern "C" void kernel_launch(void* const* d_in, const int* in_sizes, int n_in,
                              void* d_out, int out_size) {
    (void)in_sizes; (void)n_in; (void)out_size;
    const float* x   = (const float*)d_in[0];
    const float* w1q = (const float*)d_in[1];
    const float* w1s = (const float*)d_in[2];
    const float* w3q = (const float*)d_in[3];
    const float* w3s = (const float*)d_in[4];
    const float* w2q = (const float*)d_in[5];
    const float* w2s = (const float*)d_in[6];
    float* out = (float*)d_out;

    float *xr, *gbuf, *ubuf, *act;
    cudaGetSymbolAddress((void**)&xr,   d_xr);
    cudaGetSymbolAddress((void**)&gbuf, d_g);
    cudaGetSymbolAddress((void**)&ubuf, d_u);
    cudaGetSymbolAddress((void**)&act,  d_act);

    cudaFuncSetAttribute(gemm_tf32_scaled, cudaFuncAttributeMaxDynamicSharedMemorySize, SMEM_BYTES);

    const int n4x = TDIM * HDIM / 4;
    cvt_tf32_kernel<<<(n4x + 255) / 256, 256>>>((const float4*)x, (float4*)xr, n4x);

    gemm_tf32_scaled<<<dim3(TDIM / 128, FDIM / 128), 256, SMEM_BYTES>>>(xr, w1q, w1s, gbuf, TDIM, FDIM, HDIM);
    gemm_tf32_scaled<<<dim3(TDIM / 128, FDIM / 128), 256, SMEM_BYTES>>>(xr, w3q, w3s, ubuf, TDIM, FDIM, HDIM);

    const int n4f = TDIM * FDIM / 4;
    silu_mul_kernel<<<(n4f + 255) / 256, 256>>>((const float4*)gbuf, (const float4*)ubuf, (float4*)act, n4f);

    gemm_tf32_scaled<<<dim3(TDIM / 128, HDIM / 128), 256, SMEM_BYTES>>>(act, w2q, w2s, out, TDIM, HDIM, FDIM);
}

// round 3
// speedup vs baseline: 2.1193x; 2.1193x over previous
#include <cuda_runtime.h>
#include <cuda_fp16.h>
#include <cstdint>
#include <cstddef>

#define TDIM 4096
#define HDIM 2048
#define FDIM 7168

// ---------------- GEMM tile config (fp16 mma.sync) ----------------
#define BM 128
#define BN 128
#define BK 64                         // K per stage: 64 fp16 = 128B rows
#define STG 4
#define AST (BM * BK * 2)             // 16384 B
#define BST (BN * BK * 2)             // 16384 B
#define STB (AST + BST)               // 32768 B
#define SMEMB (STG * STB)             // 131072 B

// ---------------- scratch (no allocations allowed) ----------------
__device__ __half d_xh[(size_t)TDIM * HDIM];
__device__ __half d_w1h[(size_t)FDIM * HDIM];
__device__ __half d_w3h[(size_t)FDIM * HDIM];
__device__ __half d_w2h[(size_t)HDIM * FDIM];
__device__ float  d_g[(size_t)TDIM * FDIM];
__device__ float  d_u[(size_t)TDIM * FDIM];
__device__ __half d_acth[(size_t)TDIM * FDIM];

// ---------------- helpers ----------------
__device__ __forceinline__ uint32_t smem_u32(const void* p) {
    uint32_t a;
    asm("{ .reg .u64 t; cvta.to.shared.u64 t, %1; cvt.u32.u64 %0, t; }" : "=r"(a) : "l"(p));
    return a;
}
__device__ __forceinline__ void cp_async16(uint32_t dst, const void* src) {
    asm volatile("cp.async.cg.shared.global [%0], [%1], 16;\n" :: "r"(dst), "l"(src));
}
__device__ __forceinline__ void cp_commit() { asm volatile("cp.async.commit_group;\n"); }
template <int N>
__device__ __forceinline__ void cp_wait() { asm volatile("cp.async.wait_group %0;\n" :: "n"(N)); }

__device__ __forceinline__ void ldm_x4(uint32_t* r, uint32_t addr) {
    asm volatile("ldmatrix.sync.aligned.m8n8.x4.shared.b16 {%0,%1,%2,%3}, [%4];"
                 : "=r"(r[0]), "=r"(r[1]), "=r"(r[2]), "=r"(r[3]) : "r"(addr));
}
__device__ __forceinline__ void mma_f16(float* d, const uint32_t* a, const uint32_t* b) {
    asm volatile(
        "mma.sync.aligned.m16n8k16.row.col.f32.f16.f16.f32 "
        "{%0,%1,%2,%3}, {%4,%5,%6,%7}, {%8,%9}, {%0,%1,%2,%3};\n"
        : "+f"(d[0]), "+f"(d[1]), "+f"(d[2]), "+f"(d[3])
        : "r"(a[0]), "r"(a[1]), "r"(a[2]), "r"(a[3]), "r"(b[0]), "r"(b[1]));
}

// ---------------- elementwise kernels ----------------
__global__ void f32tof16_kernel(const float4* __restrict__ in, uint2* __restrict__ out, int n4) {
    int i = blockIdx.x * blockDim.x + threadIdx.x;
    if (i < n4) {
        float4 v = in[i];
        __half2 h0 = __floats2half2_rn(v.x, v.y);
        __half2 h1 = __floats2half2_rn(v.z, v.w);
        out[i] = make_uint2(*reinterpret_cast<uint32_t*>(&h0), *reinterpret_cast<uint32_t*>(&h1));
    }
}

__global__ void silu_mul_f16_kernel(const float4* __restrict__ g, const float4* __restrict__ u,
                                    uint2* __restrict__ out, int n4) {
    int i = blockIdx.x * blockDim.x + threadIdx.x;
    if (i < n4) {
        float4 gv = g[i], uv = u[i];
        float r0 = gv.x / (1.0f + __expf(-gv.x)) * uv.x;
        float r1 = gv.y / (1.0f + __expf(-gv.y)) * uv.y;
        float r2 = gv.z / (1.0f + __expf(-gv.z)) * uv.z;
        float r3 = gv.w / (1.0f + __expf(-gv.w)) * uv.w;
        __half2 h0 = __floats2half2_rn(r0, r1);
        __half2 h1 = __floats2half2_rn(r2, r3);
        out[i] = make_uint2(*reinterpret_cast<uint32_t*>(&h0), *reinterpret_cast<uint32_t*>(&h1));
    }
}

// ---------------- fp16 mma.sync GEMM with K-block scale folding ----------------
// C[m,n] = sum_kb S[n/128, kb] * sum_{k in kb} A[m,k] * B[n,k]
// A: [M,K] fp16 row-major, B: [N,K] fp16 row-major (raw fp8 values, exact in fp16)
// grid = (M/128, N/128); 256 threads; warp tile 64x32.
__global__ __launch_bounds__(256, 1)
void gemm_f16(const __half* __restrict__ A, const __half* __restrict__ B,
              const float* __restrict__ S, float* __restrict__ C,
              int M, int N, int K)
{
    extern __shared__ char smem[];
    const uint32_t sb = smem_u32(smem);
    const int tid = threadIdx.x;
    const int wid = tid >> 5, lane = tid & 31;
    const int bm = blockIdx.x, bn = blockIdx.y;
    const int wm = wid & 1, wn = wid >> 1;

    const __half* Ab = A + (size_t)bm * BM * K;
    const __half* Bb = B + (size_t)bn * BN * K;
    const int KT = K >> 6;              // 64-k tiles
    const int KB = K >> 7;              // 128-k scale blocks
    const float* Srow = S + (size_t)bn * KB;

    auto load_tile = [&](int kt) {
        const int s = kt & (STG - 1);
        const uint32_t ab = sb + s * STB;
        const uint32_t bb = ab + AST;
        const int k0 = kt << 6;
        #pragma unroll
        for (int t = 0; t < 4; t++) {           // A: 1024 x 16B chunks
            int idx = tid + t * 256;
            int row = idx >> 3, c = idx & 7;
            uint32_t off = (uint32_t)(row << 7) + (c << 4);
            uint32_t sw = off ^ ((off >> 3) & 0x70);
            cp_async16(ab + sw, Ab + (size_t)row * K + k0 + c * 8);
        }
        #pragma unroll
        for (int t = 0; t < 4; t++) {           // B: 1024 x 16B chunks
            int idx = tid + t * 256;
            int row = idx >> 3, c = idx & 7;
            uint32_t off = (uint32_t)(row << 7) + (c << 4);
            uint32_t sw = off ^ ((off >> 3) & 0x70);
            cp_async16(bb + sw, Bb + (size_t)row * K + k0 + c * 8);
        }
        cp_commit();
    };

    float acc[4][4][4];
    #pragma unroll
    for (int mt = 0; mt < 4; mt++)
        #pragma unroll
        for (int nt = 0; nt < 4; nt++)
            #pragma unroll
            for (int i = 0; i < 4; i++) acc[mt][nt][i] = 0.0f;

    #pragma unroll
    for (int s = 0; s < STG - 1; s++) load_tile(s);

    float s_cur = __ldg(Srow);

    for (int kt = 0; kt < KT; kt++) {
        if (kt && !(kt & 1)) {                  // entering new 128-k scale block
            float sn = __ldg(Srow + (kt >> 1));
            float r = s_cur / sn;
            s_cur = sn;
            #pragma unroll
            for (int mt = 0; mt < 4; mt++)
                #pragma unroll
                for (int nt = 0; nt < 4; nt++)
                    #pragma unroll
                    for (int i = 0; i < 4; i++) acc[mt][nt][i] *= r;
        }

        cp_wait<STG - 2>();
        __syncthreads();

        const int pf = kt + STG - 1;
        if (pf < KT) load_tile(pf); else cp_commit();

        const uint32_t ab = sb + (kt & (STG - 1)) * STB;
        const uint32_t bb = ab + AST;
        const int mat = lane >> 3, mr = lane & 7;

        #pragma unroll
        for (int ks = 0; ks < 4; ks++) {
            uint32_t af[4][4], bf[2][4];
            #pragma unroll
            for (int mt = 0; mt < 4; mt++) {
                int row = wm * 64 + mt * 16 + (mat & 1) * 8 + mr;
                uint32_t off = (uint32_t)(row << 7) + ks * 32 + (mat >> 1) * 16;
                uint32_t sw = off ^ ((off >> 3) & 0x70);
                ldm_x4(af[mt], ab + sw);
            }
            #pragma unroll
            for (int bq = 0; bq < 2; bq++) {
                int nrow = wn * 32 + (bq * 2 + (mat >> 1)) * 8 + mr;
                uint32_t off = (uint32_t)(nrow << 7) + ks * 32 + (mat & 1) * 16;
                uint32_t sw = off ^ ((off >> 3) & 0x70);
                ldm_x4(bf[bq], bb + sw);
            }
            #pragma unroll
            for (int mt = 0; mt < 4; mt++)
                #pragma unroll
                for (int nt = 0; nt < 4; nt++)
                    mma_f16(acc[mt][nt], af[mt], &bf[nt >> 1][(nt & 1) * 2]);
        }
    }

    // epilogue: scale by last block's S, write fp32
    const int g = lane >> 2, t4 = lane & 3;
    #pragma unroll
    for (int mt = 0; mt < 4; mt++) {
        int r0 = bm * BM + wm * 64 + mt * 16 + g;
        #pragma unroll
        for (int nt = 0; nt < 4; nt++) {
            int c0 = bn * BN + wn * 32 + nt * 8 + t4 * 2;
            float2 v0 = make_float2(acc[mt][nt][0] * s_cur, acc[mt][nt][1] * s_cur);
            float2 v1 = make_float2(acc[mt][nt][2] * s_cur, acc[mt][nt][3] * s_cur);
            *reinterpret_cast<float2*>(&C[(size_t)r0 * N + c0]) = v0;
            *reinterpret_cast<float2*>(&C[(size_t)(r0 + 8) * N + c0]) = v1;
        }
    }
}

// ---------------- launch ----------------
extern "C" void kernel_launch(void* const* d_in, const int* in_sizes, int n_in,
                              void* d_out, int out_size) {
    (void)in_sizes; (void)n_in; (void)out_size;
    const float* x   = (const float*)d_in[0];
    const float* w1q = (const float*)d_in[1];
    const float* w1s = (const float*)d_in[2];
    const float* w3q = (const float*)d_in[3];
    const float* w3s = (const float*)d_in[4];
    const float* w2q = (const float*)d_in[5];
    const float* w2s = (const float*)d_in[6];
    float* out = (float*)d_out;

    __half *xh, *w1h, *w3h, *w2h, *acth;
    float *gbuf, *ubuf;
    cudaGetSymbolAddress((void**)&xh,   d_xh);
    cudaGetSymbolAddress((void**)&w1h,  d_w1h);
    cudaGetSymbolAddress((void**)&w3h,  d_w3h);
    cudaGetSymbolAddress((void**)&w2h,  d_w2h);
    cudaGetSymbolAddress((void**)&gbuf, d_g);
    cudaGetSymbolAddress((void**)&ubuf, d_u);
    cudaGetSymbolAddress((void**)&acth, d_acth);

    cudaFuncSetAttribute(gemm_f16, cudaFuncAttributeMaxDynamicSharedMemorySize, SMEMB);

    const int n4x = TDIM * HDIM / 4;
    f32tof16_kernel<<<(n4x + 255) / 256, 256>>>((const float4*)x, (uint2*)xh, n4x);

    const int n4w1 = FDIM * HDIM / 4;
    f32tof16_kernel<<<(n4w1 + 255) / 256, 256>>>((const float4*)w1q, (uint2*)w1h, n4w1);
    f32tof16_kernel<<<(n4w1 + 255) / 256, 256>>>((const float4*)w3q, (uint2*)w3h, n4w1);
    const int n4w2 = HDIM * FDIM / 4;
    f32tof16_kernel<<<(n4w2 + 255) / 256, 256>>>((const float4*)w2q, (uint2*)w2h, n4w2);

    gemm_f16<<<dim3(TDIM / BM, FDIM / BN), 256, SMEMB>>>(xh, w1h, w1s, gbuf, TDIM, FDIM, HDIM);
    gemm_f16<<<dim3(TDIM / BM, FDIM / BN), 256, SMEMB>>>(xh, w3h, w3s, ubuf, TDIM, FDIM, HDIM);

    const int n4f = TDIM * FDIM / 4;
    silu_mul_f16_kernel<<<(n4f + 255) / 256, 256>>>((const float4*)gbuf, (const float4*)ubuf,
                                                    (uint2*)acth, n4f);

    gemm_f16<<<dim3(TDIM / BM, HDIM / BN), 256, SMEMB>>>(acth, w2h, w2s, out, TDIM, HDIM, FDIM);
}

// round 5
// speedup vs baseline: 2.5411x; 1.1990x over previous
#include <cuda_runtime.h>
#include <cuda_fp16.h>
#include <cstdint>
#include <cstddef>

#define TDIM 4096
#define HDIM 2048
#define FDIM 7168

// ---------------- GEMM tile config (fp16 mma.sync) ----------------
#define BM 128
#define BN 256
#define BK 64                         // K per stage: 64 fp16 = 128B rows
#define STG 4
#define AST (BM * BK * 2)             // 16384 B
#define BST (BN * BK * 2)             // 32768 B
#define STB (AST + BST)               // 49152 B
#define SMEMB (STG * STB)             // 196608 B

// ---------------- scratch (no allocations allowed) ----------------
__device__ __half d_xh[(size_t)TDIM * HDIM];
__device__ __half d_w1h[(size_t)FDIM * HDIM];
__device__ __half d_w3h[(size_t)FDIM * HDIM];
__device__ __half d_w2h[(size_t)HDIM * FDIM];
__device__ float  d_g[(size_t)TDIM * FDIM];
__device__ float  d_u[(size_t)TDIM * FDIM];
__device__ __half d_acth[(size_t)TDIM * FDIM];

// ---------------- helpers ----------------
__device__ __forceinline__ uint32_t smem_u32(const void* p) {
    uint32_t a;
    asm("{ .reg .u64 t; cvta.to.shared.u64 t, %1; cvt.u32.u64 %0, t; }" : "=r"(a) : "l"(p));
    return a;
}
__device__ __forceinline__ void cp_async16(uint32_t dst, const void* src) {
    asm volatile("cp.async.cg.shared.global [%0], [%1], 16;\n" :: "r"(dst), "l"(src));
}
__device__ __forceinline__ void cp_commit() { asm volatile("cp.async.commit_group;\n"); }
template <int N>
__device__ __forceinline__ void cp_wait() { asm volatile("cp.async.wait_group %0;\n" :: "n"(N)); }

__device__ __forceinline__ void ldm_x4(uint32_t* r, uint32_t addr) {
    asm volatile("ldmatrix.sync.aligned.m8n8.x4.shared.b16 {%0,%1,%2,%3}, [%4];"
                 : "=r"(r[0]), "=r"(r[1]), "=r"(r[2]), "=r"(r[3]) : "r"(addr));
}
__device__ __forceinline__ void mma_f16(float* d, const uint32_t* a, const uint32_t* b) {
    asm volatile(
        "mma.sync.aligned.m16n8k16.row.col.f32.f16.f16.f32 "
        "{%0,%1,%2,%3}, {%4,%5,%6,%7}, {%8,%9}, {%0,%1,%2,%3};\n"
        : "+f"(d[0]), "+f"(d[1]), "+f"(d[2]), "+f"(d[3])
        : "r"(a[0]), "r"(a[1]), "r"(a[2]), "r"(a[3]), "r"(b[0]), "r"(b[1]));
}

// ---------------- elementwise kernels ----------------
__global__ void f32tof16_kernel(const float4* __restrict__ in, uint2* __restrict__ out, int n4) {
    int i = blockIdx.x * blockDim.x + threadIdx.x;
    if (i < n4) {
        float4 v = in[i];
        __half2 h0 = __floats2half2_rn(v.x, v.y);
        __half2 h1 = __floats2half2_rn(v.z, v.w);
        out[i] = make_uint2(*reinterpret_cast<uint32_t*>(&h0), *reinterpret_cast<uint32_t*>(&h1));
    }
}

__global__ void silu_mul_f16_kernel(const float4* __restrict__ g, const float4* __restrict__ u,
                                    uint2* __restrict__ out, int n4) {
    int i = blockIdx.x * blockDim.x + threadIdx.x;
    if (i < n4) {
        float4 gv = g[i], uv = u[i];
        float r0 = gv.x / (1.0f + __expf(-gv.x)) * uv.x;
        float r1 = gv.y / (1.0f + __expf(-gv.y)) * uv.y;
        float r2 = gv.z / (1.0f + __expf(-gv.z)) * uv.z;
        float r3 = gv.w / (1.0f + __expf(-gv.w)) * uv.w;
        __half2 h0 = __floats2half2_rn(r0, r1);
        __half2 h1 = __floats2half2_rn(r2, r3);
        out[i] = make_uint2(*reinterpret_cast<uint32_t*>(&h0), *reinterpret_cast<uint32_t*>(&h1));
    }
}

// ---------------- fp16 mma.sync GEMM with K-block scale folding ----------------
// C[m,n] = sum_kb S[n/128, kb] * sum_{k in kb} A[m,k] * B[n,k]
// A: [M,K] fp16 row-major, B: [N,K] fp16 row-major (raw fp8 values, exact in fp16)
// grid = (M/128, N/256); 256 threads; warp tile 64x64 (2x4 warps).
__global__ __launch_bounds__(256, 1)
void gemm_f16(const __half* __restrict__ A, const __half* __restrict__ B,
              const float* __restrict__ S, float* __restrict__ C,
              int M, int N, int K)
{
    extern __shared__ char smem[];
    const uint32_t sb = smem_u32(smem);
    const int tid = threadIdx.x;
    const int wid = tid >> 5, lane = tid & 31;
    const int bm = blockIdx.x, bn = blockIdx.y;
    const int wm = wid & 1, wn = wid >> 1;       // 2 x 4 warps

    const __half* Ab = A + (size_t)bm * BM * K;
    const __half* Bb = B + (size_t)bn * BN * K;
    const int KT = K >> 6;              // 64-k tiles
    const int KB = K >> 7;              // 128-k scale blocks
    // 256-wide N block spans TWO scale rows; each 64-col warp is in one half.
    const float* Srow = S + (size_t)(bn * 2 + (wn >> 1)) * KB;

    auto load_tile = [&](int kt) {
        const int s = kt & (STG - 1);
        const uint32_t ab = sb + s * STB;
        const uint32_t bb = ab + AST;
        const int k0 = kt << 6;
        #pragma unroll
        for (int t = 0; t < 4; t++) {           // A: 1024 x 16B chunks
            int idx = tid + t * 256;
            int row = idx >> 3, c = idx & 7;
            uint32_t off = (uint32_t)(row << 7) + (c << 4);
            uint32_t sw = off ^ ((off >> 3) & 0x70);
            cp_async16(ab + sw, Ab + (size_t)row * K + k0 + c * 8);
        }
        #pragma unroll
        for (int t = 0; t < 8; t++) {           // B: 2048 x 16B chunks
            int idx = tid + t * 256;
            int row = idx >> 3, c = idx & 7;
            uint32_t off = (uint32_t)(row << 7) + (c << 4);
            uint32_t sw = off ^ ((off >> 3) & 0x70);
            cp_async16(bb + sw, Bb + (size_t)row * K + k0 + c * 8);
        }
        cp_commit();
    };

    float acc[4][8][4];
    #pragma unroll
    for (int mt = 0; mt < 4; mt++)
        #pragma unroll
        for (int nt = 0; nt < 8; nt++)
            #pragma unroll
            for (int i = 0; i < 4; i++) acc[mt][nt][i] = 0.0f;

    #pragma unroll
    for (int s = 0; s < STG - 1; s++) load_tile(s);

    float s_cur = __ldg(Srow);

    for (int kt = 0; kt < KT; kt++) {
        if (kt && !(kt & 1)) {                  // entering new 128-k scale block
            float sn = __ldg(Srow + (kt >> 1));
            float r = s_cur / sn;
            s_cur = sn;
            #pragma unroll
            for (int mt = 0; mt < 4; mt++)
                #pragma unroll
                for (int nt = 0; nt < 8; nt++)
                    #pragma unroll
                    for (int i = 0; i < 4; i++) acc[mt][nt][i] *= r;
        }

        cp_wait<STG - 2>();
        __syncthreads();

        const int pf = kt + STG - 1;
        if (pf < KT) load_tile(pf); else cp_commit();

        const uint32_t ab = sb + (kt & (STG - 1)) * STB;
        const uint32_t bb = ab + AST;
        const int mat = lane >> 3, mr = lane & 7;

        #pragma unroll
        for (int ks = 0; ks < 4; ks++) {
            uint32_t af[4][4], bf[4][4];
            #pragma unroll
            for (int mt = 0; mt < 4; mt++) {
                int row = wm * 64 + mt * 16 + (mat & 1) * 8 + mr;
                uint32_t off = (uint32_t)(row << 7) + ks * 32 + (mat >> 1) * 16;
                uint32_t sw = off ^ ((off >> 3) & 0x70);
                ldm_x4(af[mt], ab + sw);
            }
            #pragma unroll
            for (int bq = 0; bq < 4; bq++) {
                int nrow = wn * 64 + (bq * 2 + (mat >> 1)) * 8 + mr;
                uint32_t off = (uint32_t)(nrow << 7) + ks * 32 + (mat & 1) * 16;
                uint32_t sw = off ^ ((off >> 3) & 0x70);
                ldm_x4(bf[bq], bb + sw);
            }
            #pragma unroll
            for (int mt = 0; mt < 4; mt++)
                #pragma unroll
                for (int nt = 0; nt < 8; nt++)
                    mma_f16(acc[mt][nt], af[mt], &bf[nt >> 1][(nt & 1) * 2]);
        }
    }

    // epilogue: scale by this warp's last block S, write fp32
    const int g = lane >> 2, t4 = lane & 3;
    #pragma unroll
    for (int mt = 0; mt < 4; mt++) {
        int r0 = bm * BM + wm * 64 + mt * 16 + g;
        #pragma unroll
        for (int nt = 0; nt < 8; nt++) {
            int c0 = bn * BN + wn * 64 + nt * 8 + t4 * 2;
            float2 v0 = make_float2(acc[mt][nt][0] * s_cur, acc[mt][nt][1] * s_cur);
            float2 v1 = make_float2(acc[mt][nt][2] * s_cur, acc[mt][nt][3] * s_cur);
            *reinterpret_cast<float2*>(&C[(size_t)r0 * N + c0]) = v0;
            *reinterpret_cast<float2*>(&C[(size_t)(r0 + 8) * N + c0]) = v1;
        }
    }
}

// ---------------- launch ----------------
extern "C" void kernel_launch(void* const* d_in, const int* in_sizes, int n_in,
                              void* d_out, int out_size) {
    (void)in_sizes; (void)n_in; (void)out_size;
    const float* x   = (const float*)d_in[0];
    const float* w1q = (const float*)d_in[1];
    const float* w1s = (const float*)d_in[2];
    const float* w3q = (const float*)d_in[3];
    const float* w3s = (const float*)d_in[4];
    const float* w2q = (const float*)d_in[5];
    const float* w2s = (const float*)d_in[6];
    float* out = (float*)d_out;

    __half *xh, *w1h, *w3h, *w2h, *acth;
    float *gbuf, *ubuf;
    cudaGetSymbolAddress((void**)&xh,   d_xh);
    cudaGetSymbolAddress((void**)&w1h,  d_w1h);
    cudaGetSymbolAddress((void**)&w3h,  d_w3h);
    cudaGetSymbolAddress((void**)&w2h,  d_w2h);
    cudaGetSymbolAddress((void**)&gbuf, d_g);
    cudaGetSymbolAddress((void**)&ubuf, d_u);
    cudaGetSymbolAddress((void**)&acth, d_acth);

    cudaFuncSetAttribute(gemm_f16, cudaFuncAttributeMaxDynamicSharedMemorySize, SMEMB);

    const int n4x = TDIM * HDIM / 4;
    f32tof16_kernel<<<(n4x + 255) / 256, 256>>>((const float4*)x, (uint2*)xh, n4x);

    const int n4w1 = FDIM * HDIM / 4;
    f32tof16_kernel<<<(n4w1 + 255) / 256, 256>>>((const float4*)w1q, (uint2*)w1h, n4w1);
    f32tof16_kernel<<<(n4w1 + 255) / 256, 256>>>((const float4*)w3q, (uint2*)w3h, n4w1);
    const int n4w2 = HDIM * FDIM / 4;
    f32tof16_kernel<<<(n4w2 + 255) / 256, 256>>>((const float4*)w2q, (uint2*)w2h, n4w2);

    gemm_f16<<<dim3(TDIM / BM, FDIM / BN), 256, SMEMB>>>(xh, w1h, w1s, gbuf, TDIM, FDIM, HDIM);
    gemm_f16<<<dim3(TDIM / BM, FDIM / BN), 256, SMEMB>>>(xh, w3h, w3s, ubuf, TDIM, FDIM, HDIM);

    const int n4f = TDIM * FDIM / 4;
    silu_mul_f16_kernel<<<(n4f + 255) / 256, 256>>>((const float4*)gbuf, (const float4*)ubuf,
                                                    (uint2*)acth, n4f);

    gemm_f16<<<dim3(TDIM / BM, HDIM / BN), 256, SMEMB>>>(acth, w2h, w2s, out, TDIM, HDIM, FDIM);
}